// round 5
// baseline (speedup 1.0000x reference)
#include <cuda_runtime.h>

#define NB   32        // batch
#define NE   200000    // entities
#define NT   1000000   // triples
#define NR   256       // relations
#define DQ   768       // question dim
#define DIN  1280      // DQ + 2*NR
#define NEB  (NE * NB) // 6.4M floats
#define NJ   257       // 256 W_inf rows + 1 W_att row
#define NW   (NE / 32) // 6250 mask words per hop

// ---- device scratch (static; zero-initialized at load; kernels restore the
// all-zero state of g_xh / g_mask[NW..] before returning, so every call of
// kernel_launch starts from identical state). ----
__device__ float g_x0T[NEB];           // transposed seed x: [e][b] (active rows only)
__device__ float g_xh[3 * NEB];        // hop outputs, entity-major (self-cleaned)
__device__ float g_hqT[DQ * NB];       // transposed h_q: [d][b]
__device__ float g_rT[3 * NR * NB];    // r per hop: [j][b]
__device__ float g_c[3 * NB];          // attention logits per hop
__device__ unsigned g_mask[4 * NW];    // activity bitmask per hop (1..3 self-cleaned)

// ---- transpose x (B x NE) -> (NE x B), active rows only + hop-0 mask ----
__global__ void k_transpose_x(const float* __restrict__ src) {
    __shared__ float s[32][33];
    __shared__ unsigned smask;
    int lane = threadIdx.x, ty = threadIdx.y;
    if (ty == 0 && lane == 0) smask = 0;
    int cbase = blockIdx.x * 32;
#pragma unroll
    for (int row = ty; row < 32; row += 8)              // row = b
        s[row][lane] = src[(size_t)row * NE + cbase + lane];
    __syncthreads();
    unsigned local = 0;
#pragma unroll
    for (int row = ty; row < 32; row += 8) {            // row = entity offset
        float v = s[lane][row];                         // lane = b
        unsigned b = __ballot_sync(0xffffffffu, v != 0.0f);
        if (b) g_x0T[(size_t)(cbase + row) * NB + lane] = v;  // active rows only
        if (lane == 0 && b) local |= 1u << row;
    }
    if (lane == 0 && local) atomicOr(&smask, local);
    __syncthreads();
    if (ty == 0 && lane == 0) g_mask[blockIdx.x] = smask;
}

// ---- transpose h_q (B x DQ) -> (DQ x B), fused zero of r_0/c_0 accum ----
__global__ void k_prep(const float* __restrict__ src) {
    int lane = threadIdx.x, ty = threadIdx.y;
    int tid = blockIdx.x * 256 + ty * 32 + lane;
    for (int i = tid; i < NR * NB; i += 24 * 256) g_rT[i] = 0.f;
    if (tid < NB) g_c[tid] = 0.f;
    __shared__ float s[32][33];
    int cbase = blockIdx.x * 32;
#pragma unroll
    for (int row = ty; row < 32; row += 8)
        s[row][lane] = src[(size_t)row * DQ + cbase + lane];
    __syncthreads();
#pragma unroll
    for (int row = ty; row < 32; row += 8)
        g_hqT[(cbase + row) * NB + lane] = s[lane][row];
}

// ---- r_0 / c_0 = h_q @ [W_inf; W_att][:, :768].T  (split-d, atomic accum)
__global__ void k_gemm_base(const float* __restrict__ W_inf,
                            const float* __restrict__ W_att) {
    int lane = threadIdx.x, ty = threadIdx.y;
    int j = blockIdx.x;
    const float* w = (j == 256) ? W_att : W_inf + (size_t)j * DIN;
    int d0 = blockIdx.y * 192 + ty * 24;
    float a0 = 0.f, a1 = 0.f, a2 = 0.f, a3 = 0.f;
#pragma unroll
    for (int d = d0; d < d0 + 24; d += 4) {
        a0 += g_hqT[(d + 0) * NB + lane] * w[d + 0];
        a1 += g_hqT[(d + 1) * NB + lane] * w[d + 1];
        a2 += g_hqT[(d + 2) * NB + lane] * w[d + 2];
        a3 += g_hqT[(d + 3) * NB + lane] * w[d + 3];
    }
    __shared__ float s[8][32];
    s[ty][lane] = (a0 + a1) + (a2 + a3);
    __syncthreads();
    if (ty == 0) {
        float t = 0.f;
#pragma unroll
        for (int k = 0; k < 8; k++) t += s[k][lane];
        if (j == 256) atomicAdd(&g_c[lane], t);
        else          atomicAdd(&g_rT[j * NB + lane], t);
    }
}

// ---- hop 1/2 increment: out = hop0_out + r_parts @ W[:, 768:768+hop*256].T
__global__ void k_gemm_hop(const float* __restrict__ W_inf,
                           const float* __restrict__ W_att, int hop) {
    int lane = threadIdx.x, ty = threadIdx.y;
    int j = blockIdx.x;
    const float* w = (j == 256) ? W_att : W_inf + (size_t)j * DIN;
    float acc = 0.f;
    {   // most recent relation r_{hop-1}, weights w[768 .. 1024)
        const float* r1 = g_rT + (hop - 1) * NR * NB;
        const float* wd = w + DQ;
        int k0 = ty * 32;
#pragma unroll 8
        for (int k = k0; k < k0 + 32; k++)
            acc += r1[k * NB + lane] * wd[k];
    }
    if (hop == 2) {   // r_0, weights w[1024 .. 1280)
        const float* r2 = g_rT;
        const float* wd = w + DQ + NR;
        int k0 = ty * 32;
#pragma unroll 8
        for (int k = k0; k < k0 + 32; k++)
            acc += r2[k * NB + lane] * wd[k];
    }
    __shared__ float s[8][32];
    s[ty][lane] = acc;
    __syncthreads();
    if (ty == 0) {
        float t = (j == 256) ? g_c[lane] : g_rT[j * NB + lane];  // hop-0 base
#pragma unroll
        for (int k = 0; k < 8; k++) t += s[k][lane];
        if (j == 256) g_c[hop * NB + lane] = t;
        else          g_rT[hop * NR * NB + j * NB + lane] = t;
    }
}

// ---- scatter: compact active triples to smem queue, then drain with
// independent vectorized iterations (8 lanes per triple, red.v4.f32). ----
__global__ void k_scatter(const int* __restrict__ subj,
                          const int* __restrict__ rel,
                          const int* __restrict__ obj, int hop) {
    const float* __restrict__ rT = g_rT + hop * NR * NB;
    const float* __restrict__ xin = (hop == 0) ? g_x0T : (g_xh + (hop - 1) * NEB);
    float* xout = g_xh + hop * NEB;
    const unsigned* __restrict__ min_ = g_mask + hop * NW;
    unsigned* mout = g_mask + (hop + 1) * NW;

    __shared__ int qs[1024], qr[1024], qo[1024];
    __shared__ int qcnt;
    int lane = threadIdx.x & 31;
    if (threadIdx.x == 0) qcnt = 0;
    __syncthreads();

    // phase 1: test + warp-aggregated append
    int t = blockIdx.x * 1024 + threadIdx.x;
#pragma unroll
    for (int k = 0; k < 4; k++, t += 256) {
        bool act = false;
        int s_i = 0;
        if (t < NT) {
            s_i = subj[t];
            act = (min_[s_i >> 5] >> (s_i & 31)) & 1u;
        }
        unsigned bal = __ballot_sync(0xffffffffu, act);
        int cnt = __popc(bal);
        int base;
        if (lane == 0) base = cnt ? atomicAdd(&qcnt, cnt) : 0;
        base = __shfl_sync(0xffffffffu, base, 0);
        if (act) {
            int my = base + __popc(bal & ((1u << lane) - 1));
            qs[my] = s_i; qr[my] = rel[t]; qo[my] = obj[t];
        }
    }
    __syncthreads();
    int n = qcnt;
    if (n == 0) return;

    // phase 2: drain queue, 4 triples per warp-iteration, 8 lanes per triple
    int wid = threadIdx.x >> 5;
    int sub = lane >> 3, quad = lane & 7;
    for (int base = wid * 4; base < n; base += 32) {
        int e = base + sub;
        bool on = (e < n);
        float4 p = make_float4(0.f, 0.f, 0.f, 0.f);
        bool nz = false;
        int o = 0;
        if (on) {
            int s = qs[e], r = qr[e];
            o = qo[e];
            float4 xv = *reinterpret_cast<const float4*>(&xin[(size_t)s * NB + quad * 4]);
            float4 rv = *reinterpret_cast<const float4*>(&rT[r * NB + quad * 4]);
            p.x = xv.x * rv.x; p.y = xv.y * rv.y;
            p.z = xv.z * rv.z; p.w = xv.w * rv.w;
            nz = (p.x != 0.f) | (p.y != 0.f) | (p.z != 0.f) | (p.w != 0.f);
        }
        unsigned nzb = __ballot_sync(0xffffffffu, nz);
        if (nz) {
            float* dst = &xout[(size_t)o * NB + quad * 4];
            asm volatile("red.global.add.v4.f32 [%0], {%1,%2,%3,%4};"
                         :: "l"(dst), "f"(p.x), "f"(p.y), "f"(p.z), "f"(p.w)
                         : "memory");
        }
        if (on && quad == 0 && ((nzb >> (sub * 8)) & 0xffu))
            atomicOr(&mout[o >> 5], 1u << (o & 31));
    }
}

// ---- softmax + masked combine + transpose out; restores g_xh/g_mask zeros ----
__global__ void k_combine(float* __restrict__ out) {
    __shared__ float s[32][33];
    int lane = threadIdx.x, ty = threadIdx.y;
    float c0 = g_c[lane], c1 = g_c[NB + lane], c2 = g_c[2 * NB + lane];
    float m = fmaxf(c0, fmaxf(c1, c2));
    float e0 = expf(c0 - m), e1 = expf(c1 - m), e2 = expf(c2 - m);
    float inv = 1.0f / (e0 + e1 + e2);
    float a0 = e0 * inv, a1 = e1 * inv, a2 = e2 * inv;

    int bx = blockIdx.x;
    unsigned m1 = g_mask[NW + bx], m2 = g_mask[2 * NW + bx], m3 = g_mask[3 * NW + bx];
    int ebase = bx * 32;
#pragma unroll
    for (int row = ty; row < 32; row += 8) {           // row = e offset, lane = b
        int idx = (ebase + row) * NB + lane;
        float v = 0.f;
        if ((m1 >> row) & 1u) { v += a0 * g_xh[idx];            g_xh[idx] = 0.f; }
        if ((m2 >> row) & 1u) { v += a1 * g_xh[NEB + idx];      g_xh[NEB + idx] = 0.f; }
        if ((m3 >> row) & 1u) { v += a2 * g_xh[2 * NEB + idx];  g_xh[2 * NEB + idx] = 0.f; }
        s[row][lane] = v;
    }
    __syncthreads();
    if (ty == 0 && lane == 0) {       // reset masks for next call (after reads)
        g_mask[NW + bx] = 0u; g_mask[2 * NW + bx] = 0u; g_mask[3 * NW + bx] = 0u;
    }
#pragma unroll
    for (int row = ty; row < 32; row += 8)             // row = b, lane = e offset
        out[(size_t)row * NE + ebase + lane] = s[lane][row];
}

extern "C" void kernel_launch(void* const* d_in, const int* in_sizes, int n_in,
                              void* d_out, int out_size) {
    const float* x     = (const float*)d_in[0];
    const float* h_q   = (const float*)d_in[1];
    const float* W_inf = (const float*)d_in[2];
    const float* W_att = (const float*)d_in[3];
    const int*   subj  = (const int*)d_in[4];
    const int*   rel   = (const int*)d_in[5];
    const int*   obj   = (const int*)d_in[6];
    float* out = (float*)d_out;

    static cudaStream_t s1 = nullptr, s2 = nullptr;
    static cudaEvent_t eF = nullptr, e1 = nullptr, eB = nullptr,
                       eH1 = nullptr, eH2 = nullptr;
    if (!s1) {
        cudaStreamCreateWithFlags(&s1, cudaStreamNonBlocking);
        cudaStreamCreateWithFlags(&s2, cudaStreamNonBlocking);
        cudaEventCreateWithFlags(&eF,  cudaEventDisableTiming);
        cudaEventCreateWithFlags(&e1,  cudaEventDisableTiming);
        cudaEventCreateWithFlags(&eB,  cudaEventDisableTiming);
        cudaEventCreateWithFlags(&eH1, cudaEventDisableTiming);
        cudaEventCreateWithFlags(&eH2, cudaEventDisableTiming);
    }

    dim3 tb(32, 8);
    // side stream: x transpose (scatter0's data dependency)
    cudaEventRecord(eF, 0);
    cudaStreamWaitEvent(s1, eF, 0);
    k_transpose_x<<<NE / 32, tb, 0, s1>>>(x);
    cudaEventRecord(e1, s1);

    // main stream: gemm chain
    k_prep<<<DQ / 32, tb>>>(h_q);
    k_gemm_base<<<dim3(NJ, 4), tb>>>(W_inf, W_att);
    cudaEventRecord(eB, 0);
    // fork gemm hops (independent of scatters)
    cudaStreamWaitEvent(s2, eB, 0);
    k_gemm_hop<<<NJ, tb, 0, s2>>>(W_inf, W_att, 1);
    cudaEventRecord(eH1, s2);
    k_gemm_hop<<<NJ, tb, 0, s2>>>(W_inf, W_att, 2);
    cudaEventRecord(eH2, s2);

    int sblocks = (NT + 1023) / 1024;
    cudaStreamWaitEvent(0, e1, 0);
    k_scatter<<<sblocks, 256>>>(subj, rel, obj, 0);
    cudaStreamWaitEvent(0, eH1, 0);
    k_scatter<<<sblocks, 256>>>(subj, rel, obj, 1);
    cudaStreamWaitEvent(0, eH2, 0);
    k_scatter<<<sblocks, 256>>>(subj, rel, obj, 2);
    k_combine<<<NE / 32, tb>>>(out);
}

// round 6
// speedup vs baseline: 2.3895x; 2.3895x over previous
#include <cuda_runtime.h>

#define NB   32        // batch
#define NE   200000    // entities
#define NT   1000000   // triples
#define NR   256       // relations
#define DQ   768       // question dim
#define DIN  1280      // DQ + 2*NR
#define NEB  (NE * NB) // 6.4M floats
#define NJ   257       // 256 W_inf rows + 1 W_att row
#define NW   (NE / 32) // 6250 mask words per hop

// ---- device scratch (static; no allocation) ----
__device__ float g_x0T[NEB];           // transposed seed x: [e][b]
__device__ float g_xh[3 * NEB];        // hop outputs, entity-major
__device__ float g_hqT[DQ * NB];       // transposed h_q: [d][b]
__device__ float g_rT[3 * NR * NB];    // r per hop: [j][b]
__device__ float g_c[3 * NB];          // attention logits per hop
__device__ unsigned g_mask[4 * NW];    // active-entity bitmask per hop input

// ---- transpose x (B x NE) -> (NE x B) and build hop-0 activity mask ----
__global__ void k_transpose_x(const float* __restrict__ src) {
    __shared__ float s[32][33];
    __shared__ unsigned smask;
    int lane = threadIdx.x, ty = threadIdx.y;
    if (ty == 0 && lane == 0) smask = 0;
    int cbase = blockIdx.x * 32;
#pragma unroll
    for (int row = ty; row < 32; row += 8)              // row = b
        s[row][lane] = src[(size_t)row * NE + cbase + lane];
    __syncthreads();
    unsigned local = 0;
#pragma unroll
    for (int row = ty; row < 32; row += 8) {            // row = entity offset
        float v = s[lane][row];                         // lane = b
        g_x0T[(size_t)(cbase + row) * NB + lane] = v;
        unsigned b = __ballot_sync(0xffffffffu, v != 0.0f);
        if (lane == 0 && b) local |= 1u << row;
    }
    if (lane == 0 && local) atomicOr(&smask, local);
    __syncthreads();
    if (ty == 0 && lane == 0) g_mask[blockIdx.x] = smask;
}

// ---- transpose h_q (B x DQ) -> (DQ x B) ----
__global__ void k_transpose_hq(const float* __restrict__ src) {
    __shared__ float s[32][33];
    int lane = threadIdx.x, ty = threadIdx.y;
    int cbase = blockIdx.x * 32;
#pragma unroll
    for (int row = ty; row < 32; row += 8)
        s[row][lane] = src[(size_t)row * DQ + cbase + lane];
    __syncthreads();
#pragma unroll
    for (int row = ty; row < 32; row += 8)
        g_hqT[(cbase + row) * NB + lane] = s[lane][row];
}

// ---- zero all gemm accumulators (r and c, all hops) ----
__global__ void k_zero_small() {
    int i = blockIdx.x * blockDim.x + threadIdx.x;
    if (i < 3 * NR * NB) g_rT[i] = 0.f;
    if (i < 3 * NB) g_c[i] = 0.f;
}

// ---- zero hop outputs + masks 1..3 ----
__global__ void k_zero_big() {
    int i = blockIdx.x * blockDim.x + threadIdx.x;
    const int nf4 = 3 * NEB / 4;
    if (i < nf4) {
        reinterpret_cast<float4*>(g_xh)[i] = make_float4(0.f, 0.f, 0.f, 0.f);
    } else {
        int j = i - nf4;
        if (j < 3 * NW) g_mask[NW + j] = 0u;
    }
}

// ---- r_0 / c_0 = h_q @ [W_inf; W_att][:, :768].T  (split-d, atomic accum)
__global__ void k_gemm_base(const float* __restrict__ W_inf,
                            const float* __restrict__ W_att) {
    int lane = threadIdx.x, ty = threadIdx.y;
    int j = blockIdx.x;
    const float* w = (j == 256) ? W_att : W_inf + (size_t)j * DIN;
    int d0 = blockIdx.y * 192 + ty * 24;
    float a0 = 0.f, a1 = 0.f, a2 = 0.f, a3 = 0.f;
#pragma unroll
    for (int d = d0; d < d0 + 24; d += 4) {
        a0 += g_hqT[(d + 0) * NB + lane] * w[d + 0];
        a1 += g_hqT[(d + 1) * NB + lane] * w[d + 1];
        a2 += g_hqT[(d + 2) * NB + lane] * w[d + 2];
        a3 += g_hqT[(d + 3) * NB + lane] * w[d + 3];
    }
    __shared__ float s[8][32];
    s[ty][lane] = (a0 + a1) + (a2 + a3);
    __syncthreads();
    if (ty == 0) {
        float t = 0.f;
#pragma unroll
        for (int k = 0; k < 8; k++) t += s[k][lane];
        if (j == 256) atomicAdd(&g_c[lane], t);
        else          atomicAdd(&g_rT[j * NB + lane], t);
    }
}

// ---- hop 1/2 increment, split-k: out = hop0_out + r_parts @ W[:, 768:].T
// Flattened k: kk in [0, 256*hop); seg = kk>>8 selects r_{hop-1} then r_{hop-2};
// weight offset = DQ + kk. grid = (NJ, hop*2), each block covers 128 kk.
__global__ void k_gemm_hop(const float* __restrict__ W_inf,
                           const float* __restrict__ W_att, int hop) {
    int lane = threadIdx.x, ty = threadIdx.y;
    int j = blockIdx.x;
    const float* w = (j == 256) ? W_att : W_inf + (size_t)j * DIN;
    int kk0 = blockIdx.y * 128 + ty * 16;
    int seg = kk0 >> 8;                 // 16-wide slice stays in one segment
    int within = kk0 & 255;
    const float* rsrc = g_rT + (hop - 1 - seg) * NR * NB;
    const float* wd = w + DQ + kk0;
    float a0 = 0.f, a1 = 0.f;
#pragma unroll
    for (int k = 0; k < 16; k += 2) {
        a0 += rsrc[(within + k) * NB + lane] * wd[k];
        a1 += rsrc[(within + k + 1) * NB + lane] * wd[k + 1];
    }
    __shared__ float s[8][32];
    s[ty][lane] = a0 + a1;
    __syncthreads();
    if (ty == 0) {
        float t = 0.f;
#pragma unroll
        for (int k = 0; k < 8; k++) t += s[k][lane];
        if (blockIdx.y == 0)            // add hop-0 base exactly once
            t += (j == 256) ? g_c[lane] : g_rT[j * NB + lane];
        if (j == 256) atomicAdd(&g_c[hop * NB + lane], t);
        else          atomicAdd(&g_rT[hop * NR * NB + j * NB + lane], t);
    }
}

// ---- masked gather * relation -> vector scatter-add.
// Warp holds 32 triples; active ones processed 4-at-a-time, 8 lanes per
// triple, float4 per lane, one red.global.add.v4.f32 per nonzero quad. ----
__global__ void k_scatter(const int* __restrict__ subj,
                          const int* __restrict__ rel,
                          const int* __restrict__ obj, int hop) {
    const float* __restrict__ rT = g_rT + hop * NR * NB;
    const float* __restrict__ xin = (hop == 0) ? g_x0T : (g_xh + (hop - 1) * NEB);
    float* xout = g_xh + hop * NEB;
    const unsigned* __restrict__ min_ = g_mask + hop * NW;
    unsigned* mout = g_mask + (hop + 1) * NW;

    int lane = threadIdx.x & 31;
    int sub = lane >> 3, quad = lane & 7;
    int t = blockIdx.x * blockDim.x + threadIdx.x;

    int s_i = 0, r_i = 0, o_i = 0;
    bool act = false;
    if (t < NT) {
        s_i = subj[t];
        act = (min_[s_i >> 5] >> (s_i & 31)) & 1u;
        if (act) { r_i = rel[t]; o_i = obj[t]; }
    }
    unsigned bal = __ballot_sync(0xffffffffu, act);
    while (bal) {
        unsigned b = bal;
        int i0 = __ffs(b) - 1; b &= b - 1;
        int i1 = __ffs(b) - 1; b &= b - 1;
        int i2 = __ffs(b) - 1; b &= b - 1;
        int i3 = __ffs(b) - 1; b &= b - 1;
        bal = b;
        int myi = (sub == 0) ? i0 : (sub == 1) ? i1 : (sub == 2) ? i2 : i3;
        bool on = (myi >= 0);
        int src = on ? myi : 0;
        int s = __shfl_sync(0xffffffffu, s_i, src);
        int r = __shfl_sync(0xffffffffu, r_i, src);
        int o = __shfl_sync(0xffffffffu, o_i, src);
        float4 p = make_float4(0.f, 0.f, 0.f, 0.f);
        bool nz = false;
        if (on) {
            float4 xv = *reinterpret_cast<const float4*>(&xin[(size_t)s * NB + quad * 4]);
            float4 rv = *reinterpret_cast<const float4*>(&rT[r * NB + quad * 4]);
            p.x = xv.x * rv.x; p.y = xv.y * rv.y;
            p.z = xv.z * rv.z; p.w = xv.w * rv.w;
            nz = (p.x != 0.f) | (p.y != 0.f) | (p.z != 0.f) | (p.w != 0.f);
        }
        unsigned nzb = __ballot_sync(0xffffffffu, nz);
        if (nz) {
            float* dst = &xout[(size_t)o * NB + quad * 4];
            asm volatile("red.global.add.v4.f32 [%0], {%1,%2,%3,%4};"
                         :: "l"(dst), "f"(p.x), "f"(p.y), "f"(p.z), "f"(p.w)
                         : "memory");
        }
        if (on && quad == 0 && ((nzb >> (sub * 8)) & 0xffu))
            atomicOr(&mout[o >> 5], 1u << (o & 31));
    }
}

// ---- softmax + masked weighted combine, transpose back to (B,NE) ----
__global__ void k_combine(float* __restrict__ out) {
    __shared__ float s[32][33];
    int lane = threadIdx.x, ty = threadIdx.y;
    float c0 = g_c[lane], c1 = g_c[NB + lane], c2 = g_c[2 * NB + lane];
    float m = fmaxf(c0, fmaxf(c1, c2));
    float e0 = expf(c0 - m), e1 = expf(c1 - m), e2 = expf(c2 - m);
    float inv = 1.0f / (e0 + e1 + e2);
    float a0 = e0 * inv, a1 = e1 * inv, a2 = e2 * inv;

    int bx = blockIdx.x;
    unsigned m1 = g_mask[NW + bx], m2 = g_mask[2 * NW + bx], m3 = g_mask[3 * NW + bx];
    int ebase = bx * 32;
#pragma unroll
    for (int row = ty; row < 32; row += 8) {           // row = e offset, lane = b
        int idx = (ebase + row) * NB + lane;
        float v = 0.f;
        if ((m1 >> row) & 1u) v += a0 * g_xh[idx];
        if ((m2 >> row) & 1u) v += a1 * g_xh[NEB + idx];
        if ((m3 >> row) & 1u) v += a2 * g_xh[2 * NEB + idx];
        s[row][lane] = v;
    }
    __syncthreads();
#pragma unroll
    for (int row = ty; row < 32; row += 8)             // row = b, lane = e offset
        out[(size_t)row * NE + ebase + lane] = s[lane][row];
}

extern "C" void kernel_launch(void* const* d_in, const int* in_sizes, int n_in,
                              void* d_out, int out_size) {
    const float* x     = (const float*)d_in[0];
    const float* h_q   = (const float*)d_in[1];
    const float* W_inf = (const float*)d_in[2];
    const float* W_att = (const float*)d_in[3];
    const int*   subj  = (const int*)d_in[4];
    const int*   rel   = (const int*)d_in[5];
    const int*   obj   = (const int*)d_in[6];
    float* out = (float*)d_out;

    static cudaStream_t s1 = nullptr, s2 = nullptr;
    static cudaEvent_t eF = nullptr, e1 = nullptr, eB = nullptr,
                       eH1 = nullptr, eH2 = nullptr;
    if (!s1) {
        cudaStreamCreateWithFlags(&s1, cudaStreamNonBlocking);
        cudaStreamCreateWithFlags(&s2, cudaStreamNonBlocking);
        cudaEventCreateWithFlags(&eF,  cudaEventDisableTiming);
        cudaEventCreateWithFlags(&e1,  cudaEventDisableTiming);
        cudaEventCreateWithFlags(&eB,  cudaEventDisableTiming);
        cudaEventCreateWithFlags(&eH1, cudaEventDisableTiming);
        cudaEventCreateWithFlags(&eH2, cudaEventDisableTiming);
    }

    dim3 tb(32, 8);
    // fork side stream: x transpose + big zero
    cudaEventRecord(eF, 0);
    cudaStreamWaitEvent(s1, eF, 0);
    k_transpose_x<<<NE / 32, tb, 0, s1>>>(x);
    {
        int zthreads = 3 * NEB / 4 + 3 * NW;
        k_zero_big<<<(zthreads + 255) / 256, 256, 0, s1>>>();
    }
    cudaEventRecord(e1, s1);

    // main stream: gemm chain prerequisites
    k_zero_small<<<(3 * NR * NB + 255) / 256, 256>>>();
    k_transpose_hq<<<DQ / 32, tb>>>(h_q);
    k_gemm_base<<<dim3(NJ, 4), tb>>>(W_inf, W_att);
    cudaEventRecord(eB, 0);
    // fork gemm hops (independent of scatters)
    cudaStreamWaitEvent(s2, eB, 0);
    k_gemm_hop<<<dim3(NJ, 2), tb, 0, s2>>>(W_inf, W_att, 1);
    cudaEventRecord(eH1, s2);
    k_gemm_hop<<<dim3(NJ, 4), tb, 0, s2>>>(W_inf, W_att, 2);
    cudaEventRecord(eH2, s2);

    int sblocks = (NT + 255) / 256;
    cudaStreamWaitEvent(0, e1, 0);
    k_scatter<<<sblocks, 256>>>(subj, rel, obj, 0);
    cudaStreamWaitEvent(0, eH1, 0);
    k_scatter<<<sblocks, 256>>>(subj, rel, obj, 1);
    cudaStreamWaitEvent(0, eH2, 0);
    k_scatter<<<sblocks, 256>>>(subj, rel, obj, 2);
    k_combine<<<NE / 32, tb>>>(out);
}